// round 13
// baseline (speedup 1.0000x reference)
#include <cuda_runtime.h>
#include <cstdint>
#include <math.h>

#define BB 16
#define NN 325
#define DD 64
#define HH 4
#define STEPS 12
#define MAXD 64
#define CLX 8
#define TPB 768
#define NWARP (TPB/32)   // 24
#define RPC 41           // slots per CTA: ranks 0-6 -> 41, rank 7 -> 38
#define QSLOT 2          // slots per warp (slots 2w, 2w+1)

// ---- dynamic smem layout (float offsets), float4 areas 16B-aligned ----
#define OFF_W     0        // 8192
#define OFF_X     8192     // 2624
#define OFF_H     10816    // 20800
#define OFF_ED    31616    // 1312
#define OFF_AL    32928    // 24*2*64*4 = 12288  (per warp, per row-slot)
#define OFF_ES    45216    // 176
#define OFF_WMAX  45392    // 96
#define OFF_AS    45488    // 128
#define OFF_AD    45616    // 128
#define OFF_W2    45744    // 64
#define OFF_B1    45808    // 64
#define OFF_CNT   45872    // 48
#define OFF_IDX   45920    // 2624
#define OFF_MAP   48544    // 48 (slot -> true row)
#define OFF_MBAR  48592    // 4 floats (mbarrier, 16B-aligned)
#define SMEM_FLOATS 48608
#define SMEM_BYTES (SMEM_FLOATS*4)   // 194432 B

// ---------------- global scratch (static: no allocations) ----------------
__device__ float g_h  [2][BB*NN*DD];
__device__ float g_ed4[2][BB*NN*HH];    // interleaved: [node*4 + head]
__device__ float g_W1t[DD*DD];          // W1 transposed: [c*64 + k]
__device__ int   g_adj_cnt[NN];
__device__ int   g_adj_idx[NN*MAXD];
__device__ int   g_rowmap[NN];          // slot -> row (degree-balanced pairs)

// ---------------- prep: adjacency CSR (ordered, zero-padded) + W1^T ------
__global__ void prep_kernel(const float* __restrict__ graph,
                            const float* __restrict__ W1)
{
    int gt = blockIdx.x * blockDim.x + threadIdx.x;
    for (int i = gt; i < DD*DD; i += gridDim.x * blockDim.x)
        g_W1t[(i & 63) * DD + (i >> 6)] = W1[i];

    int gwarp = gt >> 5;
    int lane  = threadIdx.x & 31;
    if (gwarp >= NN) return;
    const int i = gwarp;
    const float* row = graph + (size_t)i * NN;
    int c = 0;
    for (int j0 = 0; j0 < NN; j0 += 32) {
        int j = j0 + lane;
        bool v = (j < NN) && (row[j] > 0.9f || j == i);
        unsigned m = __ballot_sync(0xffffffffu, v);
        if (v) {
            int pos = c + __popc(m & ((1u << lane) - 1u));
            if (pos < MAXD) g_adj_idx[i * MAXD + pos] = j;
        }
        c += __popc(m);
    }
    int cc = (c > MAXD) ? MAXD : c;
    // pad tail with node 0 (alpha is forced to 0 there)
    for (int p = cc + lane; p < MAXD; p += 32)
        g_adj_idx[i * MAXD + p] = 0;
    if (lane == 0) g_adj_cnt[i] = cc;
}

// ---------------- prep2: degree-balanced slot permutation -----------------
// rank rows by (degree, id); slot pairs (2k, 2k+1) receive ranks (k, 324-k)
__global__ void prep2_kernel()
{
    __shared__ int sdeg[NN];
    int t = threadIdx.x;
    if (t < NN) sdeg[t] = g_adj_cnt[t];
    __syncthreads();
    if (t < NN) {
        int d = sdeg[t];
        int rank = 0;
        for (int j = 0; j < NN; ++j) {
            int dj = sdeg[j];
            rank += (dj < d) || (dj == d && j < t);
        }
        int slot = (rank <= (NN - 1) / 2) ? 2 * rank
                                          : 2 * (NN - 1 - rank) + 1;
        g_rowmap[slot] = t;
    }
}

__device__ __forceinline__ void cluster_sync_rel()
{
    asm volatile("fence.acq_rel.cluster;" ::: "memory");
    asm volatile("barrier.cluster.arrive.aligned;" ::: "memory");
    asm volatile("barrier.cluster.wait.aligned;"   ::: "memory");
}

__device__ __forceinline__ void cp_bulk(unsigned int sdst, const void* gsrc,
                                        unsigned int bytes, unsigned int mbar)
{
    asm volatile(
        "cp.async.bulk.shared::cta.global.mbarrier::complete_tx::bytes "
        "[%0], [%1], %2, [%3];"
        :: "r"(sdst), "l"(gsrc), "r"(bytes), "r"(mbar) : "memory");
}

__device__ __forceinline__ void mbar_expect_tx(unsigned int mbar, unsigned int bytes)
{
    asm volatile("mbarrier.arrive.expect_tx.shared.b64 _, [%0], %1;"
                 :: "r"(mbar), "r"(bytes) : "memory");
}

__device__ __forceinline__ void mbar_wait(unsigned int mbar, unsigned int parity)
{
    asm volatile(
        "{\n\t"
        ".reg .pred P;\n"
        "W%=:\n\t"
        "mbarrier.try_wait.parity.acquire.cta.shared::cta.b64 P, [%0], %1;\n\t"
        "@P bra D%=;\n\t"
        "bra W%=;\n"
        "D%=:\n\t"
        "}"
        :: "r"(mbar), "r"(parity) : "memory");
}

__device__ __forceinline__ float f4c(const float4& v, int kk)
{
    return (kk == 0) ? v.x : (kk == 1) ? v.y : (kk == 2) ? v.z : v.w;
}

// ---------------- readout: out = tanh(row@W1 + b1) @ W2 + b2 -------------
__device__ __forceinline__ void warp_readout(
    const float* __restrict__ rb, const float* __restrict__ sB1,
    const float* __restrict__ sW2v, float bias2,
    float* __restrict__ outp, int lane)
{
    const float4* W1t4 = reinterpret_cast<const float4*>(g_W1t);
    float s0 = sB1[lane], s1 = sB1[lane + 32];
    #pragma unroll
    for (int k4 = 0; k4 < 16; ++k4) {
        float4 yv = reinterpret_cast<const float4*>(rb)[k4];
        float4 w0 = W1t4[lane * 16 + k4];
        float4 w1 = W1t4[(lane + 32) * 16 + k4];
        s0 += yv.x*w0.x + yv.y*w0.y + yv.z*w0.z + yv.w*w0.w;
        s1 += yv.x*w1.x + yv.y*w1.y + yv.z*w1.z + yv.w*w1.w;
    }
    float t = tanhf(s0) * sW2v[lane] + tanhf(s1) * sW2v[lane + 32];
    #pragma unroll
    for (int off = 16; off; off >>= 1)
        t += __shfl_xor_sync(0xffffffffu, t, off);
    if (lane == 0) *outp = t + bias2;
}

// ---------------- main: one 8-CTA cluster per batch -----------------------
__global__ void __launch_bounds__(TPB, 1) __cluster_dims__(CLX, 1, 1)
ode_kernel(const float* __restrict__ y0,
           const float* __restrict__ Wg,
           const float* __restrict__ a_src,
           const float* __restrict__ a_dst,
           const float* __restrict__ b1,
           const float* __restrict__ W2,
           const float* __restrict__ b2,
           float* __restrict__ out)
{
    extern __shared__ float sm[];
    float* sW    = sm + OFF_W;
    float* sX    = sm + OFF_X;
    float* sH    = sm + OFF_H;
    float* sED   = sm + OFF_ED;
    float* sAl   = sm + OFF_AL;
    float* sEs   = sm + OFF_ES;
    float* sWMax = sm + OFF_WMAX;
    float* sAS   = sm + OFF_AS;
    float* sAD   = sm + OFF_AD;
    float* sW2v  = sm + OFF_W2;
    float* sB1   = sm + OFF_B1;
    int*   sCnt  = (int*)(sm + OFF_CNT);
    int*   sIdx  = (int*)(sm + OFF_IDX);
    int*   sMap  = (int*)(sm + OFF_MAP);
    const unsigned int sHu32 =
        (unsigned int)__cvta_generic_to_shared(sH);
    const unsigned int mbarA =
        (unsigned int)__cvta_generic_to_shared(sm + OFF_MBAR);

    const int b    = blockIdx.x / CLX;
    const int rank = blockIdx.x % CLX;
    const int tid  = threadIdx.x;
    const int wid  = tid >> 5;
    const int lane = tid & 31;
    const int hsel = lane >> 3;          // head owned by this lane
    const int base  = rank * RPC;
    const int nrows = (rank == CLX - 1) ? (NN - base) : RPC;

    for (int i = tid; i < 2*DD*DD; i += TPB) sW[i] = Wg[i];
    for (int i = tid; i < 2*DD;    i += TPB) { sAS[i] = a_src[i]; sAD[i] = a_dst[i]; }
    for (int i = tid; i < DD;      i += TPB) { sW2v[i] = W2[i]; sB1[i] = b1[i]; }
    for (int i = tid; i < nrows;   i += TPB) sMap[i] = g_rowmap[base + i];
    if (tid == 0)
        asm volatile("mbarrier.init.shared.b64 [%0], 1;" :: "r"(mbarA) : "memory");
    const float bias2 = b2[0];

    const size_t bo = (size_t)b * NN * DD;

    // warp owns slots 2*wid, 2*wid+1 in ALL phases; q = slot index
    float yR[QSLOT][2], accR[QSLOT][2], invR[QSLOT];
    unsigned int ph = 0;   // mbarrier phase parity (uniform across threads)

    __syncthreads();       // sMap ready
    for (int i = tid; i < nrows; i += TPB) sCnt[i] = g_adj_cnt[sMap[i]];
    for (int i = tid; i < nrows*MAXD; i += TPB)
        sIdx[i] = g_adj_idx[sMap[i >> 6] * MAXD + (i & 63)];
    // ---- init y/x (own slots, lane owns channels 2l, 2l+1) ----
    #pragma unroll
    for (int q = 0; q < QSLOT; ++q) {
        const int r = 2*wid + q;
        if (r < nrows) {
            const size_t ro = bo + (size_t)sMap[r] * DD;
            float2 yv = *reinterpret_cast<const float2*>(y0 + ro + 2*lane);
            yR[q][0] = yv.x; yR[q][1] = yv.y;
            *reinterpret_cast<float2*>(sX + r*DD + 2*lane) = yv;
        }
    }
    __syncthreads();
    // ---- t=0 readout (from sX, warp-strided) ----
    for (int r = wid; r < nrows; r += NWARP)
        warp_readout(sX + r*DD, sB1, sW2v, bias2,
                     out + ((size_t)(b*(STEPS+1) + 0))*NN + sMap[r], lane);

    for (int s = 0; s < STEPS; ++s) {
        const float dt = (float)(s+1)*0.1f - (float)s*0.1f;
        for (int st = 0; st < 4; ++st) {
            for (int l = 0; l < 2; ++l) {
                // ======= Phase A: h = x@W, e_src, e_dst (own slots) =======
                {
                    const float* Wl = sW + l*DD*DD;
                    const float2* w2p = reinterpret_cast<const float2*>(Wl);
                    const int r0 = wid * 2;
                    if (r0 < nrows) {
                        int rl0 = r0;
                        int rl1 = (r0 + 1 > nrows-1) ? nrows-1 : r0 + 1;
                        float a0x=0,a0y=0,a1x=0,a1y=0;
                        const float4* x4 = reinterpret_cast<const float4*>(sX);
                        #pragma unroll 4
                        for (int k4 = 0; k4 < 16; ++k4) {
                            float4 x0 = x4[rl0*16 + k4];
                            float4 x1 = x4[rl1*16 + k4];
                            #pragma unroll
                            for (int kk = 0; kk < 4; ++kk) {
                                float2 w = w2p[(k4*4+kk)*32 + lane];
                                float c0 = f4c(x0,kk), c1 = f4c(x1,kk);
                                a0x += c0*w.x; a0y += c0*w.y;
                                a1x += c1*w.x; a1y += c1*w.y;
                            }
                        }
                        float ax[QSLOT] = {a0x, a1x};
                        float ay[QSLOT] = {a0y, a1y};
                        #pragma unroll
                        for (int q = 0; q < QSLOT; ++q) {
                            if (r0 + q >= nrows) break;
                            const int row = sMap[r0 + q];
                            float* hp = g_h[l] + bo + (size_t)row*DD;
                            __stcg(reinterpret_cast<float2*>(hp + 2*lane),
                                   make_float2(ax[q], ay[q]));
                            float ves = ax[q]*sAS[l*DD + 2*lane] + ay[q]*sAS[l*DD + 2*lane + 1];
                            float ved = ax[q]*sAD[l*DD + 2*lane] + ay[q]*sAD[l*DD + 2*lane + 1];
                            #pragma unroll
                            for (int off = 4; off; off >>= 1) {
                                ves += __shfl_down_sync(0xffffffffu, ves, off, 8);
                                ved += __shfl_down_sync(0xffffffffu, ved, off, 8);
                            }
                            if ((lane & 7) == 0) {
                                sEs[(r0 + q)*4 + hsel] = ves;
                                __stcg(g_ed4[l] + ((size_t)b*NN + row)*4 + hsel, ved);
                            }
                        }
                    }
                }
                cluster_sync_rel();
                // ======= bulk-DMA copy of ALL h rows (1 thread issues) ====
                if (tid == 0) {
                    mbar_expect_tx(mbarA, NN*256u);
                    cp_bulk(sHu32, g_h[l] + bo, NN*256u, mbarA);
                }
                // ======= ED copy + per-head global max =====================
                {
                    float4 mv = make_float4(-3e38f, -3e38f, -3e38f, -3e38f);
                    if (tid < NN) {
                        float4 ev = __ldcg(reinterpret_cast<const float4*>(
                            g_ed4[l] + (size_t)b*NN*HH) + tid);
                        reinterpret_cast<float4*>(sED)[tid] = ev;
                        mv = ev;
                    }
                    #pragma unroll
                    for (int off = 16; off; off >>= 1) {
                        mv.x = fmaxf(mv.x, __shfl_xor_sync(0xffffffffu, mv.x, off));
                        mv.y = fmaxf(mv.y, __shfl_xor_sync(0xffffffffu, mv.y, off));
                        mv.z = fmaxf(mv.z, __shfl_xor_sync(0xffffffffu, mv.z, off));
                        mv.w = fmaxf(mv.w, __shfl_xor_sync(0xffffffffu, mv.w, off));
                    }
                    if (lane == 0)
                        reinterpret_cast<float4*>(sWMax)[wid] = mv;
                }
                __syncthreads();   // sED + sWMax ready for softmax
                // ======= softmax (single fused pass; global-max shift) ====
                {
                    float4 mg = (lane < NWARP)
                        ? reinterpret_cast<const float4*>(sWMax)[lane]
                        : make_float4(-3e38f, -3e38f, -3e38f, -3e38f);
                    #pragma unroll
                    for (int off = 16; off; off >>= 1) {
                        mg.x = fmaxf(mg.x, __shfl_xor_sync(0xffffffffu, mg.x, off));
                        mg.y = fmaxf(mg.y, __shfl_xor_sync(0xffffffffu, mg.y, off));
                        mg.z = fmaxf(mg.z, __shfl_xor_sync(0xffffffffu, mg.z, off));
                        mg.w = fmaxf(mg.w, __shfl_xor_sync(0xffffffffu, mg.w, off));
                    }
                    #pragma unroll
                    for (int q = 0; q < QSLOT; ++q) {
                        const int r = 2*wid + q;
                        if (r >= nrows) break;
                        const int cnt  = sCnt[r];
                        const int cnt8 = (cnt + 7) & ~7;
                        const int* idxr = sIdx + r * MAXD;
                        float4* aw = reinterpret_cast<float4*>(sAl)
                                   + (wid*QSLOT + q) * MAXD;
                        float4 esv = reinterpret_cast<const float4*>(sEs)[r];
                        float4 sh;
                        sh.x = esv.x + mg.x; sh.x = fmaxf(sh.x, 0.2f*sh.x);
                        sh.y = esv.y + mg.y; sh.y = fmaxf(sh.y, 0.2f*sh.y);
                        sh.z = esv.z + mg.z; sh.z = fmaxf(sh.z, 0.2f*sh.z);
                        sh.w = esv.w + mg.w; sh.w = fmaxf(sh.w, 0.2f*sh.w);
                        float s0=0.f, s1=0.f, s2=0.f, s3=0.f;
                        for (int j0 = lane; j0 < cnt8; j0 += 32) {
                            int j = idxr[j0];
                            float4 ev = reinterpret_cast<const float4*>(sED)[j];
                            float e0 = esv.x + ev.x; e0 = fmaxf(e0, 0.2f*e0);
                            float e1 = esv.y + ev.y; e1 = fmaxf(e1, 0.2f*e1);
                            float e2 = esv.z + ev.z; e2 = fmaxf(e2, 0.2f*e2);
                            float e3 = esv.w + ev.w; e3 = fmaxf(e3, 0.2f*e3);
                            float p0 = __expf(e0 - sh.x);
                            float p1 = __expf(e1 - sh.y);
                            float p2 = __expf(e2 - sh.z);
                            float p3 = __expf(e3 - sh.w);
                            if (j0 >= cnt) { p0 = 0.f; p1 = 0.f; p2 = 0.f; p3 = 0.f; }
                            aw[j0] = make_float4(p0, p1, p2, p3);
                            s0 += p0; s1 += p1; s2 += p2; s3 += p3;
                        }
                        #pragma unroll
                        for (int off = 16; off; off >>= 1) {
                            s0 += __shfl_xor_sync(0xffffffffu, s0, off);
                            s1 += __shfl_xor_sync(0xffffffffu, s1, off);
                            s2 += __shfl_xor_sync(0xffffffffu, s2, off);
                            s3 += __shfl_xor_sync(0xffffffffu, s3, off);
                        }
                        const float ssum = (hsel == 0) ? s0 : (hsel == 1) ? s1
                                         : (hsel == 2) ? s2 : s3;
                        invR[q] = 1.f / ssum;
                    }
                }
                mbar_wait(mbarA, ph);
                ph ^= 1u;
                // ======= Phase B: SpMM (own slots; no block sync needed) ==
                {
                    const float2* h2 = reinterpret_cast<const float2*>(sH);
                    #pragma unroll
                    for (int q = 0; q < QSLOT; ++q) {
                        const int r = 2*wid + q;
                        if (r >= nrows) break;
                        const int cnt8 = (sCnt[r] + 7) & ~7;
                        const int* idxr = sIdx + r * MAXD;
                        const float* awf = sAl + (wid*QSLOT + q) * MAXD * 4;
                        float acc0 = 0.f, acc1 = 0.f;
                        for (int j0 = 0; j0 < cnt8; j0 += 8) {
                            int jj[8]; float al[8]; float2 hv[8];
                            #pragma unroll
                            for (int u = 0; u < 8; ++u) jj[u] = idxr[j0+u];
                            #pragma unroll
                            for (int u = 0; u < 8; ++u)
                                al[u] = awf[(j0+u)*4 + hsel];
                            #pragma unroll
                            for (int u = 0; u < 8; ++u)
                                hv[u] = h2[jj[u]*32 + lane];
                            #pragma unroll
                            for (int u = 0; u < 8; ++u) {
                                acc0 += al[u]*hv[u].x;
                                acc1 += al[u]*hv[u].y;
                            }
                        }
                        float k0 = acc0 * invR[q];
                        float k1 = acc1 * invR[q];
                        // ---- fused epilogue (registers -> sX, own slot) ---
                        float2* xr2 = reinterpret_cast<float2*>(sX + r*DD) + lane;
                        if (l == 0) {
                            float2 xv;
                            xv.x = (k0 > 0.f) ? k0 : (__expf(k0) - 1.f);
                            xv.y = (k1 > 0.f) ? k1 : (__expf(k1) - 1.f);
                            *xr2 = xv;
                        } else {
                            if (st == 0) { accR[q][0] = k0; accR[q][1] = k1; }
                            else {
                                float w = (st == 3) ? 1.f : 2.f;
                                accR[q][0] += w * k0; accR[q][1] += w * k1;
                            }
                            if (st < 3) {
                                float cc = (st == 2) ? dt : 0.5f * dt;
                                *xr2 = make_float2(yR[q][0] + cc * k0,
                                                   yR[q][1] + cc * k1);
                            } else {
                                yR[q][0] += dt * (1.f/6.f) * accR[q][0];
                                yR[q][1] += dt * (1.f/6.f) * accR[q][1];
                                *xr2 = make_float2(yR[q][0], yR[q][1]);
                            }
                        }
                    }
                }
            } // l
        } // st
        // ---- readout for t = s+1 (sX holds y; cross-warp read) ----
        __syncthreads();
        for (int r = wid; r < nrows; r += NWARP)
            warp_readout(sX + r*DD, sB1, sW2v, bias2,
                         out + ((size_t)(b*(STEPS+1) + s + 1))*NN + sMap[r], lane);
        // next cluster barrier orders these reads vs future sX writes
    } // s
}

extern "C" void kernel_launch(void* const* d_in, const int* in_sizes, int n_in,
                              void* d_out, int out_size)
{
    const float* y0    = (const float*)d_in[0];
    const float* graph = (const float*)d_in[1];
    const float* Wg    = (const float*)d_in[2];
    const float* a_src = (const float*)d_in[3];
    const float* a_dst = (const float*)d_in[4];
    const float* W1    = (const float*)d_in[5];
    const float* b1    = (const float*)d_in[6];
    const float* W2    = (const float*)d_in[7];
    const float* b2    = (const float*)d_in[8];
    float* out = (float*)d_out;

    cudaFuncSetAttribute(ode_kernel,
                         cudaFuncAttributeMaxDynamicSharedMemorySize, SMEM_BYTES);
    prep_kernel<<<41, 256>>>(graph, W1);
    prep2_kernel<<<1, 352>>>();
    ode_kernel<<<BB*CLX, TPB, SMEM_BYTES>>>(y0, Wg, a_src, a_dst, b1, W2, b2, out);
}

// round 14
// speedup vs baseline: 1.0683x; 1.0683x over previous
#include <cuda_runtime.h>
#include <cstdint>
#include <math.h>

#define BB 16
#define NN 325
#define DD 64
#define HH 4
#define STEPS 12
#define MAXD 64
#define CLX 8
#define TPB 768
#define NWARP (TPB/32)   // 24
#define RPC 41           // rows per CTA: ranks 0-6 -> 41, rank 7 -> 38
#define QSLOT 2          // rows per warp (rows 2w, 2w+1)

// ---- dynamic smem layout (float offsets), float4 areas 16B-aligned ----
#define OFF_W     0        // 8192
#define OFF_X     8192     // 2624
#define OFF_H     10816    // 20800
#define OFF_AL    31616    // 24*2*64*4 = 12288
#define OFF_ES    43904    // 176
#define OFF_AS    44080    // 128
#define OFF_AD    44208    // 128
#define OFF_W2    44336    // 64
#define OFF_B1    44400    // 64
#define OFF_CNT   44464    // 48
#define OFF_IDX   44512    // 2624
#define OFF_MBAR  47136    // 4 floats (mbarrier, 16B-aligned)
#define SMEM_FLOATS 47152
#define SMEM_BYTES (SMEM_FLOATS*4)   // 188608 B

// ---------------- global scratch (static: no allocations) ----------------
__device__ float g_h  [2][BB*NN*DD];
__device__ float g_ed4[2][BB*NN*HH];    // interleaved: [node*4 + head]
__device__ float g_W1t[DD*DD];          // W1 transposed: [c*64 + k]
__device__ int   g_adj_cnt[NN];
__device__ int   g_adj_idx[NN*MAXD];

// ---------------- prep: adjacency CSR (ordered, zero-padded) + W1^T ------
__global__ void prep_kernel(const float* __restrict__ graph,
                            const float* __restrict__ W1)
{
    int gt = blockIdx.x * blockDim.x + threadIdx.x;
    for (int i = gt; i < DD*DD; i += gridDim.x * blockDim.x)
        g_W1t[(i & 63) * DD + (i >> 6)] = W1[i];

    int gwarp = gt >> 5;
    int lane  = threadIdx.x & 31;
    if (gwarp >= NN) return;
    const int i = gwarp;
    const float* row = graph + (size_t)i * NN;
    int c = 0;
    for (int j0 = 0; j0 < NN; j0 += 32) {
        int j = j0 + lane;
        bool v = (j < NN) && (row[j] > 0.9f || j == i);
        unsigned m = __ballot_sync(0xffffffffu, v);
        if (v) {
            int pos = c + __popc(m & ((1u << lane) - 1u));
            if (pos < MAXD) g_adj_idx[i * MAXD + pos] = j;
        }
        c += __popc(m);
    }
    int cc = (c > MAXD) ? MAXD : c;
    // pad tail with node 0 (alpha is forced to 0 there)
    for (int p = cc + lane; p < MAXD; p += 32)
        g_adj_idx[i * MAXD + p] = 0;
    if (lane == 0) g_adj_cnt[i] = cc;
}

__device__ __forceinline__ void cluster_sync_rel()
{
    asm volatile("fence.acq_rel.cluster;" ::: "memory");
    asm volatile("barrier.cluster.arrive.aligned;" ::: "memory");
    asm volatile("barrier.cluster.wait.aligned;"   ::: "memory");
}

__device__ __forceinline__ void cp_bulk(unsigned int sdst, const void* gsrc,
                                        unsigned int bytes, unsigned int mbar)
{
    asm volatile(
        "cp.async.bulk.shared::cta.global.mbarrier::complete_tx::bytes "
        "[%0], [%1], %2, [%3];"
        :: "r"(sdst), "l"(gsrc), "r"(bytes), "r"(mbar) : "memory");
}

__device__ __forceinline__ void mbar_expect_tx(unsigned int mbar, unsigned int bytes)
{
    asm volatile("mbarrier.arrive.expect_tx.shared.b64 _, [%0], %1;"
                 :: "r"(mbar), "r"(bytes) : "memory");
}

__device__ __forceinline__ void mbar_wait(unsigned int mbar, unsigned int parity)
{
    asm volatile(
        "{\n\t"
        ".reg .pred P;\n"
        "W%=:\n\t"
        "mbarrier.try_wait.parity.acquire.cta.shared::cta.b64 P, [%0], %1;\n\t"
        "@P bra D%=;\n\t"
        "bra W%=;\n"
        "D%=:\n\t"
        "}"
        :: "r"(mbar), "r"(parity) : "memory");
}

__device__ __forceinline__ float f4c(const float4& v, int kk)
{
    return (kk == 0) ? v.x : (kk == 1) ? v.y : (kk == 2) ? v.z : v.w;
}

// ---------------- readout: out = tanh(row@W1 + b1) @ W2 + b2 -------------
__device__ __forceinline__ void warp_readout(
    const float* __restrict__ rb, const float* __restrict__ sB1,
    const float* __restrict__ sW2v, float bias2,
    float* __restrict__ outp, int lane)
{
    const float4* W1t4 = reinterpret_cast<const float4*>(g_W1t);
    float s0 = sB1[lane], s1 = sB1[lane + 32];
    #pragma unroll
    for (int k4 = 0; k4 < 16; ++k4) {
        float4 yv = reinterpret_cast<const float4*>(rb)[k4];
        float4 w0 = W1t4[lane * 16 + k4];
        float4 w1 = W1t4[(lane + 32) * 16 + k4];
        s0 += yv.x*w0.x + yv.y*w0.y + yv.z*w0.z + yv.w*w0.w;
        s1 += yv.x*w1.x + yv.y*w1.y + yv.z*w1.z + yv.w*w1.w;
    }
    float t = tanhf(s0) * sW2v[lane] + tanhf(s1) * sW2v[lane + 32];
    #pragma unroll
    for (int off = 16; off; off >>= 1)
        t += __shfl_xor_sync(0xffffffffu, t, off);
    if (lane == 0) *outp = t + bias2;
}

// ---------------- main: one 8-CTA cluster per batch -----------------------
__global__ void __launch_bounds__(TPB, 1) __cluster_dims__(CLX, 1, 1)
ode_kernel(const float* __restrict__ y0,
           const float* __restrict__ Wg,
           const float* __restrict__ a_src,
           const float* __restrict__ a_dst,
           const float* __restrict__ b1,
           const float* __restrict__ W2,
           const float* __restrict__ b2,
           float* __restrict__ out)
{
    extern __shared__ float sm[];
    float* sW    = sm + OFF_W;
    float* sX    = sm + OFF_X;
    float* sH    = sm + OFF_H;
    float* sAl   = sm + OFF_AL;
    float* sEs   = sm + OFF_ES;
    float* sAS   = sm + OFF_AS;
    float* sAD   = sm + OFF_AD;
    float* sW2v  = sm + OFF_W2;
    float* sB1   = sm + OFF_B1;
    int*   sCnt  = (int*)(sm + OFF_CNT);
    int*   sIdx  = (int*)(sm + OFF_IDX);
    const unsigned int sHu32 =
        (unsigned int)__cvta_generic_to_shared(sH);
    const unsigned int mbarA =
        (unsigned int)__cvta_generic_to_shared(sm + OFF_MBAR);

    const int b    = blockIdx.x / CLX;
    const int rank = blockIdx.x % CLX;
    const int tid  = threadIdx.x;
    const int wid  = tid >> 5;
    const int lane = tid & 31;
    const int hsel = lane >> 3;          // head owned by this lane
    const int base  = rank * RPC;
    const int nrows = (rank == CLX - 1) ? (NN - base) : RPC;

    for (int i = tid; i < 2*DD*DD; i += TPB) sW[i] = Wg[i];
    for (int i = tid; i < 2*DD;    i += TPB) { sAS[i] = a_src[i]; sAD[i] = a_dst[i]; }
    for (int i = tid; i < DD;      i += TPB) { sW2v[i] = W2[i]; sB1[i] = b1[i]; }
    for (int i = tid; i < nrows;   i += TPB) sCnt[i] = g_adj_cnt[base + i];
    for (int i = tid; i < nrows*MAXD; i += TPB)
        sIdx[i] = g_adj_idx[base*MAXD + i];
    if (tid == 0)
        asm volatile("mbarrier.init.shared.b64 [%0], 1;" :: "r"(mbarA) : "memory");
    const float bias2 = b2[0];

    const size_t bo = (size_t)b * NN * DD;

    // warp owns rows 2*wid, 2*wid+1 in ALL phases; q = row slot
    float yR[QSLOT][2], accR[QSLOT][2], invR[QSLOT];
    unsigned int ph = 0;   // mbarrier phase parity (uniform across threads)

    __syncthreads();
    // ---- init y/x (own rows, lane owns channels 2l, 2l+1) ----
    #pragma unroll
    for (int q = 0; q < QSLOT; ++q) {
        const int r = 2*wid + q;
        if (r < nrows) {
            const size_t ro = bo + (size_t)(base + r) * DD;
            float2 yv = *reinterpret_cast<const float2*>(y0 + ro + 2*lane);
            yR[q][0] = yv.x; yR[q][1] = yv.y;
            *reinterpret_cast<float2*>(sX + r*DD + 2*lane) = yv;
        }
    }
    __syncthreads();
    // ---- t=0 readout (from sX, warp-strided) ----
    for (int r = wid; r < nrows; r += NWARP)
        warp_readout(sX + r*DD, sB1, sW2v, bias2,
                     out + ((size_t)(b*(STEPS+1) + 0))*NN + base + r, lane);

    for (int s = 0; s < STEPS; ++s) {
        const float dt = (float)(s+1)*0.1f - (float)s*0.1f;
        for (int st = 0; st < 4; ++st) {
            for (int l = 0; l < 2; ++l) {
                // ======= Phase A: h = x@W, e_src, e_dst (own rows only) ===
                {
                    const float* Wl = sW + l*DD*DD;
                    const float2* w2p = reinterpret_cast<const float2*>(Wl);
                    const int r0 = wid * 2;
                    if (r0 < nrows) {
                        int rl0 = r0;
                        int rl1 = (r0 + 1 > nrows-1) ? nrows-1 : r0 + 1;
                        float a0x=0,a0y=0,a1x=0,a1y=0;
                        const float4* x4 = reinterpret_cast<const float4*>(sX);
                        #pragma unroll 4
                        for (int k4 = 0; k4 < 16; ++k4) {
                            float4 x0 = x4[rl0*16 + k4];
                            float4 x1 = x4[rl1*16 + k4];
                            #pragma unroll
                            for (int kk = 0; kk < 4; ++kk) {
                                float2 w = w2p[(k4*4+kk)*32 + lane];
                                float c0 = f4c(x0,kk), c1 = f4c(x1,kk);
                                a0x += c0*w.x; a0y += c0*w.y;
                                a1x += c1*w.x; a1y += c1*w.y;
                            }
                        }
                        float ax[QSLOT] = {a0x, a1x};
                        float ay[QSLOT] = {a0y, a1y};
                        #pragma unroll
                        for (int q = 0; q < QSLOT; ++q) {
                            if (r0 + q >= nrows) break;
                            const int row = base + r0 + q;
                            float* hp = g_h[l] + bo + (size_t)row*DD;
                            __stcg(reinterpret_cast<float2*>(hp + 2*lane),
                                   make_float2(ax[q], ay[q]));
                            float ves = ax[q]*sAS[l*DD + 2*lane] + ay[q]*sAS[l*DD + 2*lane + 1];
                            float ved = ax[q]*sAD[l*DD + 2*lane] + ay[q]*sAD[l*DD + 2*lane + 1];
                            #pragma unroll
                            for (int off = 4; off; off >>= 1) {
                                ves += __shfl_down_sync(0xffffffffu, ves, off, 8);
                                ved += __shfl_down_sync(0xffffffffu, ved, off, 8);
                            }
                            if ((lane & 7) == 0) {
                                sEs[(r0 + q)*4 + hsel] = ves;
                                __stcg(g_ed4[l] + ((size_t)b*NN + row)*4 + hsel, ved);
                            }
                        }
                    }
                }
                cluster_sync_rel();
                // ======= bulk-DMA copy of ALL h rows (1 thread issues) ====
                if (tid == 0) {
                    mbar_expect_tx(mbarA, NN*256u);
                    cp_bulk(sHu32, g_h[l] + bo, NN*256u, mbarA);
                }
                // ======= softmax: no shift (|e| ~ O(1) << 88), ed via L2 ==
                {
                    const float4* edg = reinterpret_cast<const float4*>(
                        g_ed4[l] + (size_t)b*NN*HH);
                    #pragma unroll
                    for (int q = 0; q < QSLOT; ++q) {
                        const int r = 2*wid + q;
                        if (r >= nrows) break;
                        const int cnt  = sCnt[r];
                        const int cnt8 = (cnt + 7) & ~7;
                        const int* idxr = sIdx + r * MAXD;
                        float4* aw = reinterpret_cast<float4*>(sAl)
                                   + (wid*QSLOT + q) * MAXD;
                        float4 esv = reinterpret_cast<const float4*>(sEs)[r];
                        float s0=0.f, s1=0.f, s2=0.f, s3=0.f;
                        for (int j0 = lane; j0 < cnt8; j0 += 32) {
                            int j = idxr[j0];
                            float4 ev = __ldcg(edg + j);
                            float e0 = esv.x + ev.x; e0 = fmaxf(e0, 0.2f*e0);
                            float e1 = esv.y + ev.y; e1 = fmaxf(e1, 0.2f*e1);
                            float e2 = esv.z + ev.z; e2 = fmaxf(e2, 0.2f*e2);
                            float e3 = esv.w + ev.w; e3 = fmaxf(e3, 0.2f*e3);
                            float p0 = __expf(e0);
                            float p1 = __expf(e1);
                            float p2 = __expf(e2);
                            float p3 = __expf(e3);
                            if (j0 >= cnt) { p0 = 0.f; p1 = 0.f; p2 = 0.f; p3 = 0.f; }
                            aw[j0] = make_float4(p0, p1, p2, p3);
                            s0 += p0; s1 += p1; s2 += p2; s3 += p3;
                        }
                        #pragma unroll
                        for (int off = 16; off; off >>= 1) {
                            s0 += __shfl_xor_sync(0xffffffffu, s0, off);
                            s1 += __shfl_xor_sync(0xffffffffu, s1, off);
                            s2 += __shfl_xor_sync(0xffffffffu, s2, off);
                            s3 += __shfl_xor_sync(0xffffffffu, s3, off);
                        }
                        const float ssum = (hsel == 0) ? s0 : (hsel == 1) ? s1
                                         : (hsel == 2) ? s2 : s3;
                        invR[q] = 1.f / ssum;
                    }
                }
                mbar_wait(mbarA, ph);
                ph ^= 1u;
                // ======= Phase B: SpMM (own rows; no block sync needed) ===
                {
                    const float2* h2 = reinterpret_cast<const float2*>(sH);
                    #pragma unroll
                    for (int q = 0; q < QSLOT; ++q) {
                        const int r = 2*wid + q;
                        if (r >= nrows) break;
                        const int cnt8 = (sCnt[r] + 7) & ~7;
                        const int* idxr = sIdx + r * MAXD;
                        const float* awf = sAl + (wid*QSLOT + q) * MAXD * 4;
                        float acc0 = 0.f, acc1 = 0.f;
                        for (int j0 = 0; j0 < cnt8; j0 += 8) {
                            int jj[8]; float al[8]; float2 hv[8];
                            #pragma unroll
                            for (int u = 0; u < 8; ++u) jj[u] = idxr[j0+u];
                            #pragma unroll
                            for (int u = 0; u < 8; ++u)
                                al[u] = awf[(j0+u)*4 + hsel];
                            #pragma unroll
                            for (int u = 0; u < 8; ++u)
                                hv[u] = h2[jj[u]*32 + lane];
                            #pragma unroll
                            for (int u = 0; u < 8; ++u) {
                                acc0 += al[u]*hv[u].x;
                                acc1 += al[u]*hv[u].y;
                            }
                        }
                        float k0 = acc0 * invR[q];
                        float k1 = acc1 * invR[q];
                        // ---- fused epilogue (registers -> sX, own row) ----
                        float2* xr2 = reinterpret_cast<float2*>(sX + r*DD) + lane;
                        if (l == 0) {
                            float2 xv;
                            xv.x = (k0 > 0.f) ? k0 : (__expf(k0) - 1.f);
                            xv.y = (k1 > 0.f) ? k1 : (__expf(k1) - 1.f);
                            *xr2 = xv;
                        } else {
                            if (st == 0) { accR[q][0] = k0; accR[q][1] = k1; }
                            else {
                                float w = (st == 3) ? 1.f : 2.f;
                                accR[q][0] += w * k0; accR[q][1] += w * k1;
                            }
                            if (st < 3) {
                                float cc = (st == 2) ? dt : 0.5f * dt;
                                *xr2 = make_float2(yR[q][0] + cc * k0,
                                                   yR[q][1] + cc * k1);
                            } else {
                                yR[q][0] += dt * (1.f/6.f) * accR[q][0];
                                yR[q][1] += dt * (1.f/6.f) * accR[q][1];
                                *xr2 = make_float2(yR[q][0], yR[q][1]);
                            }
                        }
                    }
                }
            } // l
        } // st
        // ---- readout for t = s+1 (sX holds y; cross-warp read) ----
        __syncthreads();
        for (int r = wid; r < nrows; r += NWARP)
            warp_readout(sX + r*DD, sB1, sW2v, bias2,
                         out + ((size_t)(b*(STEPS+1) + s + 1))*NN + base + r, lane);
        // next cluster barrier orders these reads vs future sX writes
    } // s
}

extern "C" void kernel_launch(void* const* d_in, const int* in_sizes, int n_in,
                              void* d_out, int out_size)
{
    const float* y0    = (const float*)d_in[0];
    const float* graph = (const float*)d_in[1];
    const float* Wg    = (const float*)d_in[2];
    const float* a_src = (const float*)d_in[3];
    const float* a_dst = (const float*)d_in[4];
    const float* W1    = (const float*)d_in[5];
    const float* b1    = (const float*)d_in[6];
    const float* W2    = (const float*)d_in[7];
    const float* b2    = (const float*)d_in[8];
    float* out = (float*)d_out;

    cudaFuncSetAttribute(ode_kernel,
                         cudaFuncAttributeMaxDynamicSharedMemorySize, SMEM_BYTES);
    prep_kernel<<<41, 256>>>(graph, W1);
    ode_kernel<<<BB*CLX, TPB, SMEM_BYTES>>>(y0, Wg, a_src, a_dst, b1, W2, b2, out);
}

// round 15
// speedup vs baseline: 1.0683x; 1.0000x over previous
#include <cuda_runtime.h>
#include <cstdint>
#include <math.h>

#define BB 16
#define NN 325
#define DD 64
#define HH 4
#define STEPS 12
#define MAXD 64
#define CLX 8
#define TPB 768
#define NWARP (TPB/32)   // 24
#define RPC 41           // rows per CTA: ranks 0-6 -> 41, rank 7 -> 38
#define QSLOT 2          // rows per warp (rows 2w, 2w+1)

// ---- dynamic smem layout (float offsets), float4 areas 16B-aligned ----
#define OFF_W     0        // 8192
#define OFF_X     8192     // 2624
#define OFF_H     10816    // 20800
#define OFF_AL    31616    // 24*2*64*4 = 12288
#define OFF_ES    43904    // 176
#define OFF_AS    44080    // 128
#define OFF_AD    44208    // 128
#define OFF_W2    44336    // 64
#define OFF_B1    44400    // 64
#define OFF_CNT   44464    // 48
#define OFF_IDX   44512    // 2624
#define OFF_MBAR  47136    // 4 floats (mbarrier, 16B-aligned)
#define SMEM_FLOATS 47152
#define SMEM_BYTES (SMEM_FLOATS*4)   // 188608 B

// ---------------- global scratch (static: no allocations) ----------------
__device__ float g_h  [2][BB*NN*DD];
__device__ float g_ed4[2][BB*NN*HH];    // interleaved: [node*4 + head]
__device__ float g_W1t[DD*DD];          // W1 transposed: [c*64 + k]
__device__ int   g_adj_cnt[NN];
__device__ int   g_adj_idx[NN*MAXD];

// ---------------- prep: adjacency CSR (ordered, zero-padded) + W1^T ------
__global__ void prep_kernel(const float* __restrict__ graph,
                            const float* __restrict__ W1)
{
    int gt = blockIdx.x * blockDim.x + threadIdx.x;
    for (int i = gt; i < DD*DD; i += gridDim.x * blockDim.x)
        g_W1t[(i & 63) * DD + (i >> 6)] = W1[i];

    int gwarp = gt >> 5;
    int lane  = threadIdx.x & 31;
    if (gwarp >= NN) return;
    const int i = gwarp;
    const float* row = graph + (size_t)i * NN;
    int c = 0;
    for (int j0 = 0; j0 < NN; j0 += 32) {
        int j = j0 + lane;
        bool v = (j < NN) && (row[j] > 0.9f || j == i);
        unsigned m = __ballot_sync(0xffffffffu, v);
        if (v) {
            int pos = c + __popc(m & ((1u << lane) - 1u));
            if (pos < MAXD) g_adj_idx[i * MAXD + pos] = j;
        }
        c += __popc(m);
    }
    int cc = (c > MAXD) ? MAXD : c;
    // pad tail with node 0 (alpha is forced to 0 there)
    for (int p = cc + lane; p < MAXD; p += 32)
        g_adj_idx[i * MAXD + p] = 0;
    if (lane == 0) g_adj_cnt[i] = cc;
}

__device__ __forceinline__ void cluster_sync_rel()
{
    asm volatile("fence.acq_rel.cluster;" ::: "memory");
    asm volatile("barrier.cluster.arrive.aligned;" ::: "memory");
    asm volatile("barrier.cluster.wait.aligned;"   ::: "memory");
}

__device__ __forceinline__ void cp_bulk(unsigned int sdst, const void* gsrc,
                                        unsigned int bytes, unsigned int mbar)
{
    asm volatile(
        "cp.async.bulk.shared::cta.global.mbarrier::complete_tx::bytes "
        "[%0], [%1], %2, [%3];"
        :: "r"(sdst), "l"(gsrc), "r"(bytes), "r"(mbar) : "memory");
}

__device__ __forceinline__ void mbar_expect_tx(unsigned int mbar, unsigned int bytes)
{
    asm volatile("mbarrier.arrive.expect_tx.shared.b64 _, [%0], %1;"
                 :: "r"(mbar), "r"(bytes) : "memory");
}

__device__ __forceinline__ void mbar_wait(unsigned int mbar, unsigned int parity)
{
    asm volatile(
        "{\n\t"
        ".reg .pred P;\n"
        "W%=:\n\t"
        "mbarrier.try_wait.parity.acquire.cta.shared::cta.b64 P, [%0], %1;\n\t"
        "@P bra D%=;\n\t"
        "bra W%=;\n"
        "D%=:\n\t"
        "}"
        :: "r"(mbar), "r"(parity) : "memory");
}

__device__ __forceinline__ float f4c(const float4& v, int kk)
{
    return (kk == 0) ? v.x : (kk == 1) ? v.y : (kk == 2) ? v.z : v.w;
}

// ---------------- readout: out = tanh(row@W1 + b1) @ W2 + b2 -------------
__device__ __forceinline__ void warp_readout(
    const float* __restrict__ rb, const float* __restrict__ sB1,
    const float* __restrict__ sW2v, float bias2,
    float* __restrict__ outp, int lane)
{
    const float4* W1t4 = reinterpret_cast<const float4*>(g_W1t);
    float s0 = sB1[lane], s1 = sB1[lane + 32];
    #pragma unroll
    for (int k4 = 0; k4 < 16; ++k4) {
        float4 yv = reinterpret_cast<const float4*>(rb)[k4];
        float4 w0 = W1t4[lane * 16 + k4];
        float4 w1 = W1t4[(lane + 32) * 16 + k4];
        s0 += yv.x*w0.x + yv.y*w0.y + yv.z*w0.z + yv.w*w0.w;
        s1 += yv.x*w1.x + yv.y*w1.y + yv.z*w1.z + yv.w*w1.w;
    }
    float t = tanhf(s0) * sW2v[lane] + tanhf(s1) * sW2v[lane + 32];
    #pragma unroll
    for (int off = 16; off; off >>= 1)
        t += __shfl_xor_sync(0xffffffffu, t, off);
    if (lane == 0) *outp = t + bias2;
}

// ---------------- main: one 8-CTA cluster per batch -----------------------
__global__ void __launch_bounds__(TPB, 1) __cluster_dims__(CLX, 1, 1)
ode_kernel(const float* __restrict__ y0,
           const float* __restrict__ Wg,
           const float* __restrict__ a_src,
           const float* __restrict__ a_dst,
           const float* __restrict__ b1,
           const float* __restrict__ W2,
           const float* __restrict__ b2,
           float* __restrict__ out)
{
    extern __shared__ float sm[];
    float* sW    = sm + OFF_W;
    float* sX    = sm + OFF_X;
    float* sH    = sm + OFF_H;
    float* sAl   = sm + OFF_AL;
    float* sEs   = sm + OFF_ES;
    float* sAS   = sm + OFF_AS;
    float* sAD   = sm + OFF_AD;
    float* sW2v  = sm + OFF_W2;
    float* sB1   = sm + OFF_B1;
    int*   sCnt  = (int*)(sm + OFF_CNT);
    int*   sIdx  = (int*)(sm + OFF_IDX);
    const unsigned int sHu32 =
        (unsigned int)__cvta_generic_to_shared(sH);
    const unsigned int mbarA =
        (unsigned int)__cvta_generic_to_shared(sm + OFF_MBAR);

    const int b    = blockIdx.x / CLX;
    const int rank = blockIdx.x % CLX;
    const int tid  = threadIdx.x;
    const int wid  = tid >> 5;
    const int lane = tid & 31;
    const int hsel = lane >> 3;          // head owned by this lane
    const int base  = rank * RPC;
    const int nrows = (rank == CLX - 1) ? (NN - base) : RPC;

    for (int i = tid; i < 2*DD*DD; i += TPB) sW[i] = Wg[i];
    for (int i = tid; i < 2*DD;    i += TPB) { sAS[i] = a_src[i]; sAD[i] = a_dst[i]; }
    for (int i = tid; i < DD;      i += TPB) { sW2v[i] = W2[i]; sB1[i] = b1[i]; }
    for (int i = tid; i < nrows;   i += TPB) sCnt[i] = g_adj_cnt[base + i];
    for (int i = tid; i < nrows*MAXD; i += TPB)
        sIdx[i] = g_adj_idx[base*MAXD + i];
    if (tid == 0)
        asm volatile("mbarrier.init.shared.b64 [%0], 1;" :: "r"(mbarA) : "memory");
    const float bias2 = b2[0];

    const size_t bo = (size_t)b * NN * DD;

    // warp owns rows 2*wid, 2*wid+1 in ALL phases; q = row slot
    float yR[QSLOT][2], accR[QSLOT][2];
    unsigned int ph = 0;   // mbarrier phase parity (uniform across threads)

    __syncthreads();
    // ---- init y/x (own rows, lane owns channels 2l, 2l+1) ----
    #pragma unroll
    for (int q = 0; q < QSLOT; ++q) {
        const int r = 2*wid + q;
        if (r < nrows) {
            const size_t ro = bo + (size_t)(base + r) * DD;
            float2 yv = *reinterpret_cast<const float2*>(y0 + ro + 2*lane);
            yR[q][0] = yv.x; yR[q][1] = yv.y;
            *reinterpret_cast<float2*>(sX + r*DD + 2*lane) = yv;
        }
    }
    __syncthreads();
    // ---- t=0 readout (from sX, warp-strided) ----
    for (int r = wid; r < nrows; r += NWARP)
        warp_readout(sX + r*DD, sB1, sW2v, bias2,
                     out + ((size_t)(b*(STEPS+1) + 0))*NN + base + r, lane);

    for (int s = 0; s < STEPS; ++s) {
        const float dt = (float)(s+1)*0.1f - (float)s*0.1f;
        for (int st = 0; st < 4; ++st) {
            for (int l = 0; l < 2; ++l) {
                // ======= Phase A: h = x@W, e_src, e_dst (own rows only) ===
                {
                    const float* Wl = sW + l*DD*DD;
                    const float2* w2p = reinterpret_cast<const float2*>(Wl);
                    const int r0 = wid * 2;
                    if (r0 < nrows) {
                        int rl0 = r0;
                        int rl1 = (r0 + 1 > nrows-1) ? nrows-1 : r0 + 1;
                        float a0x=0,a0y=0,a1x=0,a1y=0;
                        const float4* x4 = reinterpret_cast<const float4*>(sX);
                        #pragma unroll 4
                        for (int k4 = 0; k4 < 16; ++k4) {
                            float4 x0 = x4[rl0*16 + k4];
                            float4 x1 = x4[rl1*16 + k4];
                            #pragma unroll
                            for (int kk = 0; kk < 4; ++kk) {
                                float2 w = w2p[(k4*4+kk)*32 + lane];
                                float c0 = f4c(x0,kk), c1 = f4c(x1,kk);
                                a0x += c0*w.x; a0y += c0*w.y;
                                a1x += c1*w.x; a1y += c1*w.y;
                            }
                        }
                        float ax[QSLOT] = {a0x, a1x};
                        float ay[QSLOT] = {a0y, a1y};
                        #pragma unroll
                        for (int q = 0; q < QSLOT; ++q) {
                            if (r0 + q >= nrows) break;
                            const int row = base + r0 + q;
                            float* hp = g_h[l] + bo + (size_t)row*DD;
                            __stcg(reinterpret_cast<float2*>(hp + 2*lane),
                                   make_float2(ax[q], ay[q]));
                            float ves = ax[q]*sAS[l*DD + 2*lane] + ay[q]*sAS[l*DD + 2*lane + 1];
                            float ved = ax[q]*sAD[l*DD + 2*lane] + ay[q]*sAD[l*DD + 2*lane + 1];
                            #pragma unroll
                            for (int off = 4; off; off >>= 1) {
                                ves += __shfl_down_sync(0xffffffffu, ves, off, 8);
                                ved += __shfl_down_sync(0xffffffffu, ved, off, 8);
                            }
                            if ((lane & 7) == 0) {
                                sEs[(r0 + q)*4 + hsel] = ves;
                                __stcg(g_ed4[l] + ((size_t)b*NN + row)*4 + hsel, ved);
                            }
                        }
                    }
                }
                cluster_sync_rel();
                // ======= bulk-DMA copy of ALL h rows (4 chunks, 1 thread) =
                if (tid == 0) {
                    mbar_expect_tx(mbarA, NN*256u);
                    const char* hsrc = (const char*)(g_h[l] + bo);
                    cp_bulk(sHu32,          hsrc,          20800u, mbarA);
                    cp_bulk(sHu32 + 20800u, hsrc + 20800u, 20800u, mbarA);
                    cp_bulk(sHu32 + 41600u, hsrc + 41600u, 20800u, mbarA);
                    cp_bulk(sHu32 + 62400u, hsrc + 62400u, 20800u, mbarA);
                }
                // ======= softmax: 2 rows fused (no shift, no reduction) ===
                {
                    const float4* edg = reinterpret_cast<const float4*>(
                        g_ed4[l] + (size_t)b*NN*HH);
                    const int r0 = wid * 2;
                    if (r0 < nrows) {
                        const bool hasB = (r0 + 1 < nrows);
                        const int cntA = sCnt[r0];
                        const int cntB = hasB ? sCnt[r0 + 1] : 0;
                        const int c8A = (cntA + 7) & ~7;
                        const int c8B = (cntB + 7) & ~7;
                        const int cmax = (c8A > c8B) ? c8A : c8B;
                        const int* idxA = sIdx + r0 * MAXD;
                        const int* idxB = sIdx + (hasB ? (r0 + 1) : r0) * MAXD;
                        float4* awA = reinterpret_cast<float4*>(sAl)
                                    + (wid*QSLOT + 0) * MAXD;
                        float4* awB = reinterpret_cast<float4*>(sAl)
                                    + (wid*QSLOT + 1) * MAXD;
                        float4 esA = reinterpret_cast<const float4*>(sEs)[r0];
                        float4 esB = hasB
                            ? reinterpret_cast<const float4*>(sEs)[r0 + 1] : esA;
                        for (int j0 = lane; j0 < cmax; j0 += 32) {
                            // row A chain
                            if (j0 < c8A) {
                                int j = idxA[j0];
                                float4 ev = __ldcg(edg + j);
                                float e0 = esA.x + ev.x; e0 = fmaxf(e0, 0.2f*e0);
                                float e1 = esA.y + ev.y; e1 = fmaxf(e1, 0.2f*e1);
                                float e2 = esA.z + ev.z; e2 = fmaxf(e2, 0.2f*e2);
                                float e3 = esA.w + ev.w; e3 = fmaxf(e3, 0.2f*e3);
                                float p0 = __expf(e0), p1 = __expf(e1);
                                float p2 = __expf(e2), p3 = __expf(e3);
                                if (j0 >= cntA) { p0=0.f; p1=0.f; p2=0.f; p3=0.f; }
                                awA[j0] = make_float4(p0, p1, p2, p3);
                            }
                            // row B chain (independent; overlaps A's L2 latency)
                            if (hasB && j0 < c8B) {
                                int j = idxB[j0];
                                float4 ev = __ldcg(edg + j);
                                float e0 = esB.x + ev.x; e0 = fmaxf(e0, 0.2f*e0);
                                float e1 = esB.y + ev.y; e1 = fmaxf(e1, 0.2f*e1);
                                float e2 = esB.z + ev.z; e2 = fmaxf(e2, 0.2f*e2);
                                float e3 = esB.w + ev.w; e3 = fmaxf(e3, 0.2f*e3);
                                float p0 = __expf(e0), p1 = __expf(e1);
                                float p2 = __expf(e2), p3 = __expf(e3);
                                if (j0 >= cntB) { p0=0.f; p1=0.f; p2=0.f; p3=0.f; }
                                awB[j0] = make_float4(p0, p1, p2, p3);
                            }
                        }
                    }
                }
                mbar_wait(mbarA, ph);
                ph ^= 1u;
                // ======= Phase B: SpMM + inline ssum (own rows) ===========
                {
                    const float2* h2 = reinterpret_cast<const float2*>(sH);
                    #pragma unroll
                    for (int q = 0; q < QSLOT; ++q) {
                        const int r = 2*wid + q;
                        if (r >= nrows) break;
                        const int cnt8 = (sCnt[r] + 7) & ~7;
                        const int* idxr = sIdx + r * MAXD;
                        const float* awf = sAl + (wid*QSLOT + q) * MAXD * 4;
                        float acc0 = 0.f, acc1 = 0.f, ssum = 0.f;
                        for (int j0 = 0; j0 < cnt8; j0 += 8) {
                            int jj[8]; float al[8]; float2 hv[8];
                            #pragma unroll
                            for (int u = 0; u < 8; ++u) jj[u] = idxr[j0+u];
                            #pragma unroll
                            for (int u = 0; u < 8; ++u)
                                al[u] = awf[(j0+u)*4 + hsel];
                            #pragma unroll
                            for (int u = 0; u < 8; ++u)
                                hv[u] = h2[jj[u]*32 + lane];
                            #pragma unroll
                            for (int u = 0; u < 8; ++u) {
                                acc0 += al[u]*hv[u].x;
                                acc1 += al[u]*hv[u].y;
                                ssum += al[u];
                            }
                        }
                        const float inv = 1.f / ssum;
                        float k0 = acc0 * inv;
                        float k1 = acc1 * inv;
                        // ---- fused epilogue (registers -> sX, own row) ----
                        float2* xr2 = reinterpret_cast<float2*>(sX + r*DD) + lane;
                        if (l == 0) {
                            float2 xv;
                            xv.x = (k0 > 0.f) ? k0 : (__expf(k0) - 1.f);
                            xv.y = (k1 > 0.f) ? k1 : (__expf(k1) - 1.f);
                            *xr2 = xv;
                        } else {
                            if (st == 0) { accR[q][0] = k0; accR[q][1] = k1; }
                            else {
                                float w = (st == 3) ? 1.f : 2.f;
                                accR[q][0] += w * k0; accR[q][1] += w * k1;
                            }
                            if (st < 3) {
                                float cc = (st == 2) ? dt : 0.5f * dt;
                                *xr2 = make_float2(yR[q][0] + cc * k0,
                                                   yR[q][1] + cc * k1);
                            } else {
                                yR[q][0] += dt * (1.f/6.f) * accR[q][0];
                                yR[q][1] += dt * (1.f/6.f) * accR[q][1];
                                *xr2 = make_float2(yR[q][0], yR[q][1]);
                            }
                        }
                    }
                }
            } // l
        } // st
        // ---- readout for t = s+1 (sX holds y; cross-warp read) ----
        __syncthreads();
        for (int r = wid; r < nrows; r += NWARP)
            warp_readout(sX + r*DD, sB1, sW2v, bias2,
                         out + ((size_t)(b*(STEPS+1) + s + 1))*NN + base + r, lane);
        // next cluster barrier orders these reads vs future sX writes
    } // s
}

extern "C" void kernel_launch(void* const* d_in, const int* in_sizes, int n_in,
                              void* d_out, int out_size)
{
    const float* y0    = (const float*)d_in[0];
    const float* graph = (const float*)d_in[1];
    const float* Wg    = (const float*)d_in[2];
    const float* a_src = (const float*)d_in[3];
    const float* a_dst = (const float*)d_in[4];
    const float* W1    = (const float*)d_in[5];
    const float* b1    = (const float*)d_in[6];
    const float* W2    = (const float*)d_in[7];
    const float* b2    = (const float*)d_in[8];
    float* out = (float*)d_out;

    cudaFuncSetAttribute(ode_kernel,
                         cudaFuncAttributeMaxDynamicSharedMemorySize, SMEM_BYTES);
    prep_kernel<<<41, 256>>>(graph, W1);
    ode_kernel<<<BB*CLX, TPB, SMEM_BYTES>>>(y0, Wg, a_src, a_dst, b1, W2, b2, out);
}